// round 11
// baseline (speedup 1.0000x reference)
#include <cuda_runtime.h>
#include <cstdint>

#define BB 32768
#define FF 128
#define HH 64
#define NMAX 4224   // 64 L1 boundaries + 65*64 L2 kinks (worst case)
#define NB 4096     // eval bucket count
#define XLO (-5.5f)
#define XHI (5.5f)

// ---- device scratch (no cudaMalloc allowed) ----
__device__ float  g_tsort[FF * HH];
__device__ int    stage_n[FF * 65];
__device__ float  stage_kinks[FF * 65 * 64];
__device__ float2 stage_SI[FF * 65 * 65];
__device__ float  g_X[FF * NMAX];
__device__ float2 g_SI[FF * (NMAX + 1)];
__device__ int    g_N[FF];
__device__ uint16_t g_bstart[FF * NB];
__device__ float  g_xT[FF * BB];
__device__ float  g_contrib[FF * BB];

__device__ __forceinline__ float finf() { return __int_as_float(0x7f800000); }

// ---- K0: per-feature sorted layer-1 breakpoints t_h = -b1/w1 ----
__global__ void sort_t_kernel(const float* __restrict__ w1, const float* __restrict__ b1) {
    __shared__ float t[HH];
    const int f = blockIdx.x, h = threadIdx.x;
    float w = w1[f * HH + h], b = b1[f * HH + h];
    float tv;
    if (w == 0.f) tv = finf();
    else { tv = -b / w; if (tv != tv) tv = finf(); }
    t[h] = tv;
    __syncthreads();
    for (int p = 0; p < HH; ++p) {          // odd-even transposition sort
        int i = 2 * h + (p & 1);
        if (i + 1 < HH) {
            float a = t[i], c = t[i + 1];
            if (c < a) { t[i] = c; t[i + 1] = a; }
        }
        __syncthreads();
    }
    g_tsort[f * HH + h] = t[h];
}

// ---- K1: per (feature f, L1-segment s): in-segment kinks + prefix slopes ----
__global__ void build_kernel(const float* __restrict__ w1, const float* __restrict__ b1,
                             const float* __restrict__ w2, const float* __restrict__ b2,
                             const float* __restrict__ w3, const float* __restrict__ b3) {
    const int s = blockIdx.x;   // 0..64
    const int f = blockIdx.y;
    const int g = threadIdx.x;  // 0..63
    __shared__ float w1s[HH], b1s[HH];
    __shared__ float kk[HH], dsv[HH], div_[HH];
    __shared__ double red[HH], ps[HH], pi[HH];
    __shared__ float Ts[HH + 2];
    __shared__ double sS0, sI0;

    w1s[g] = w1[f * HH + g];
    b1s[g] = b1[f * HH + g];
    Ts[g + 1] = g_tsort[f * HH + g];
    if (g == 0) { Ts[0] = -finf(); Ts[HH + 1] = finf(); }
    __syncthreads();

    const float Tlo = Ts[s], Thi = Ts[s + 1];
    const bool loI = isinf(Tlo), hiI = isinf(Thi);
    float xm;
    if (!loI && !hiI)      xm = 0.5f * Tlo + 0.5f * Thi;
    else if (loI && hiI)   xm = 0.f;
    else if (loI)          xm = Thi - 1.f;
    else                   xm = Tlo + 1.f;

    // alpha_g, beta'_g for this segment (active set fixed within segment)
    float a = 0.f, be = 0.f;
    #pragma unroll 8
    for (int h = 0; h < HH; ++h) {
        if (fmaf(xm, w1s[h], b1s[h]) > 0.f) {   // uniform branch over block
            float w2v = __ldg(w2 + f * HH * HH + h * HH + g);
            a  = fmaf(w1s[h], w2v, a);
            be = fmaf(b1s[h], w2v, be);
        }
    }
    be += __ldg(b2 + f * HH + g);
    const float w3v = __ldg(w3 + f * HH + g);

    // classify relu_g within (Tlo, Thi)
    bool ev = false, baseAct = false;
    float kink = finf(), dsl = 0.f, din = 0.f;
    if (a > 0.f) {
        float xs = -be / a;
        if (xs <= Tlo) baseAct = true;
        else if (xs < Thi) { ev = true; kink = xs; dsl = w3v * a; din = w3v * be; }
    } else if (a < 0.f) {
        float xs = -be / a;
        if (xs >= Thi) baseAct = true;
        else if (xs > Tlo) { ev = true; baseAct = true;
                             kink = xs; dsl = -w3v * a; din = -w3v * be; }
    } else {
        if (be > 0.f) baseAct = true;
    }

    // S0/I0 at segment start (fp64 reduce)
    red[g] = baseAct ? (double)(w3v * a) : 0.0;
    __syncthreads();
    for (int o = 32; o > 0; o >>= 1) { if (g < o) red[g] += red[g + o]; __syncthreads(); }
    if (g == 0) sS0 = red[0];
    __syncthreads();
    red[g] = baseAct ? (double)(w3v * be) : 0.0;
    __syncthreads();
    for (int o = 32; o > 0; o >>= 1) { if (g < o) red[g] += red[g + o]; __syncthreads(); }
    if (g == 0) sI0 = red[0] + (double)__ldg(b3 + f);
    const int n = __syncthreads_count(ev ? 1 : 0);

    kk[g] = kink; dsv[g] = dsl; div_[g] = din;
    __syncthreads();

    // bitonic sort 64 (keys kk asc; non-events padded +inf)
    for (int k = 2; k <= HH; k <<= 1)
        for (int j = k >> 1; j > 0; j >>= 1) {
            int ixj = g ^ j;
            if (ixj > g) {
                bool up = ((g & k) == 0);
                if ((kk[g] > kk[ixj]) == up) {
                    float t0;
                    t0 = kk[g];   kk[g] = kk[ixj];     kk[ixj] = t0;
                    t0 = dsv[g];  dsv[g] = dsv[ixj];   dsv[ixj] = t0;
                    t0 = div_[g]; div_[g] = div_[ixj]; div_[ixj] = t0;
                }
            }
            __syncthreads();
        }

    // inclusive prefix sums of deltas (fp64)
    ps[g] = (double)dsv[g]; pi[g] = (double)div_[g];
    __syncthreads();
    for (int o = 1; o < HH; o <<= 1) {
        double vs = (g >= o) ? ps[g - o] : 0.0;
        double vi = (g >= o) ? pi[g - o] : 0.0;
        __syncthreads();
        ps[g] += vs; pi[g] += vi;
        __syncthreads();
    }

    const int fs = f * 65 + s;
    if (g == 0) {
        stage_n[fs] = n;
        stage_SI[fs * 65] = make_float2((float)sS0, (float)sI0);
    }
    if (g < n) {
        stage_kinks[fs * 64 + g] = kk[g];
        stage_SI[fs * 65 + g + 1] =
            make_float2((float)(sS0 + ps[g]), (float)(sI0 + pi[g]));
    }
}

// ---- K2: concatenate per-segment tables (naturally globally sorted) ----
__global__ void compact_kernel() {
    const int f = blockIdx.x;
    const int tid = threadIdx.x;
    __shared__ int offX[66];
    __shared__ int nsh[65];
    if (tid < 65) nsh[tid] = stage_n[f * 65 + tid];
    __syncthreads();
    if (tid == 0) {
        int c = 0;
        for (int s = 0; s < 65; ++s) { offX[s] = c; c += nsh[s] + (s < 64 ? 1 : 0); }
        offX[65] = c;
        g_N[f] = c;
    }
    __syncthreads();
    for (int s = 0; s < 65; ++s) {
        const int n = nsh[s], ox = offX[s], fs = f * 65 + s;
        for (int j = tid; j < n; j += blockDim.x)
            g_X[f * NMAX + ox + j] = stage_kinks[fs * 64 + j];
        for (int j = tid; j <= n; j += blockDim.x)
            g_SI[f * (NMAX + 1) + ox + j] = stage_SI[fs * 65 + j];
        if (s < 64 && tid == 0)
            g_X[f * NMAX + ox + n] = g_tsort[f * HH + s];
    }
}

// ---- K2b: per-feature uniform-grid bucket table (lower_bound starts) ----
__global__ __launch_bounds__(256) void bucket_kernel() {
    __shared__ float Xs[NMAX];
    const int f = blockIdx.x;
    const int N = g_N[f];
    for (int i = threadIdx.x; i < N; i += 256) Xs[i] = g_X[f * NMAX + i];
    __syncthreads();
    const float inv = (XHI - XLO) / (float)NB;
    for (int i = threadIdx.x; i < NB; i += 256) {
        float bl = XLO + (float)i * inv;
        int lo = 0, len = N;
        while (len > 0) {                    // lower_bound: first idx with X >= bl
            int half = len >> 1;
            if (Xs[lo + half] < bl) { lo += half + 1; len -= half + 1; }
            else len = half;
        }
        g_bstart[f * NB + i] = (uint16_t)lo;
    }
}

// ---- K3: transpose x (B,F) -> (F,B) for coalesced eval ----
__global__ void xT_kernel(const float* __restrict__ x) {
    __shared__ float tile[32][33];
    const int bb = blockIdx.x * 32, ff = blockIdx.y * 32;
    const int tx = threadIdx.x, ty = threadIdx.y;
    #pragma unroll
    for (int i = ty; i < 32; i += 8)
        tile[i][tx] = x[(size_t)(bb + i) * FF + ff + tx];
    __syncthreads();
    #pragma unroll
    for (int i = ty; i < 32; i += 8)
        g_xT[(size_t)(ff + i) * BB + bb + tx] = tile[tx][i];
}

// ---- K4: eval — bucket lookup + short fix-up scan + 1 FMA per (b,f) ----
__global__ __launch_bounds__(256) void eval_kernel() {
    __shared__ float Xs[NMAX];
    __shared__ uint16_t bs[NB];
    const int f = blockIdx.y;
    const int N = g_N[f];
    for (int i = threadIdx.x; i < N; i += 256) Xs[i] = g_X[f * NMAX + i];
    {
        const uint32_t* src = (const uint32_t*)(g_bstart + f * NB);
        uint32_t* dst = (uint32_t*)bs;
        for (int i = threadIdx.x; i < NB / 2; i += 256) dst[i] = src[i];
    }
    __syncthreads();
    const float scale = (float)NB / (XHI - XLO);
    const float2* SI = g_SI + (size_t)f * (NMAX + 1);
    const float* xp = g_xT + (size_t)f * BB + blockIdx.x * 4096;
    float* cp = g_contrib + (size_t)f * BB + blockIdx.x * 4096;
    for (int r = threadIdx.x; r < 4096; r += 256) {
        float xv = __ldg(xp + r);
        int k = (int)((xv - XLO) * scale);
        k = max(0, min(NB - 1, k));
        int idx = bs[k];
        // bidirectional fix-up -> exact upper_bound (robust to bucket rounding)
        while (idx > 0 && Xs[idx - 1] > xv) --idx;
        while (idx < N && Xs[idx] <= xv) ++idx;
        float2 si = __ldg(SI + idx);
        cp[r] = fmaf(si.x, xv, si.y);
    }
}

// ---- K5: finalize ----
__global__ void finalize_kernel(const float* __restrict__ bias,
                                float* __restrict__ out) {
    int b = blockIdx.x * blockDim.x + threadIdx.x;
    if (b >= BB) return;
    float l = bias[0];
    #pragma unroll 16
    for (int f = 0; f < FF; ++f) l += g_contrib[f * BB + b];
    float p = 1.0f / (1.0f + expf(-l));
    out[2 * b + 0] = 1.0f - p;
    out[2 * b + 1] = p;
}

extern "C" void kernel_launch(void* const* d_in, const int* in_sizes, int n_in,
                              void* d_out, int out_size) {
    const float* x    = (const float*)d_in[0];
    const float* w1   = (const float*)d_in[1];
    const float* b1   = (const float*)d_in[2];
    const float* w2   = (const float*)d_in[3];
    const float* b2   = (const float*)d_in[4];
    const float* w3   = (const float*)d_in[5];
    const float* b3   = (const float*)d_in[6];
    const float* bias = (const float*)d_in[7];
    float* out = (float*)d_out;

    sort_t_kernel<<<FF, HH>>>(w1, b1);
    build_kernel<<<dim3(65, FF), HH>>>(w1, b1, w2, b2, w3, b3);
    compact_kernel<<<FF, 256>>>();
    bucket_kernel<<<FF, 256>>>();
    xT_kernel<<<dim3(BB / 32, FF / 32), dim3(32, 8)>>>(x);
    eval_kernel<<<dim3(8, FF), 256>>>();
    finalize_kernel<<<BB / 256, 256>>>(bias, out);
}

// round 12
// speedup vs baseline: 1.0181x; 1.0181x over previous
#include <cuda_runtime.h>
#include <cstdint>

#define BB 32768
#define FF 128
#define HH 64
#define NMAX 4224   // 64 L1 boundaries + 65*64 L2 kinks (worst case)
#define NB 4096     // eval bucket count
#define XLO (-5.5f)
#define XHI (5.5f)

// ---- device scratch (no cudaMalloc allowed) ----
__device__ float  g_tsort[FF * HH];
__device__ int    stage_n[FF * 65];
__device__ float  stage_kinks[FF * 65 * 64];
__device__ float2 stage_SI[FF * 65 * 65];
__device__ float  g_X[FF * NMAX];
__device__ float2 g_SI[FF * (NMAX + 1)];
__device__ int    g_N[FF];
__device__ uint16_t g_bstart[FF * NB];
__device__ float  g_xT[FF * BB];
__device__ float  g_contrib[FF * BB];

__device__ __forceinline__ float finf() { return __int_as_float(0x7f800000); }

// ---- K0: per-feature sorted layer-1 breakpoints t_h = -b1/w1 ----
__global__ void sort_t_kernel(const float* __restrict__ w1, const float* __restrict__ b1) {
    __shared__ float t[HH];
    const int f = blockIdx.x, h = threadIdx.x;
    float w = w1[f * HH + h], b = b1[f * HH + h];
    float tv;
    if (w == 0.f) tv = finf();
    else { tv = -b / w; if (tv != tv) tv = finf(); }
    t[h] = tv;
    __syncthreads();
    for (int p = 0; p < HH; ++p) {          // odd-even transposition sort
        int i = 2 * h + (p & 1);
        if (i + 1 < HH) {
            float a = t[i], c = t[i + 1];
            if (c < a) { t[i] = c; t[i + 1] = a; }
        }
        __syncthreads();
    }
    g_tsort[f * HH + h] = t[h];
}

// ---- K1: per (feature f, L1-segment s): in-segment kinks + prefix slopes ----
__global__ void build_kernel(const float* __restrict__ w1, const float* __restrict__ b1,
                             const float* __restrict__ w2, const float* __restrict__ b2,
                             const float* __restrict__ w3, const float* __restrict__ b3) {
    const int s = blockIdx.x;   // 0..64
    const int f = blockIdx.y;
    const int g = threadIdx.x;  // 0..63
    __shared__ float w1s[HH], b1s[HH];
    __shared__ float kk[HH], dsv[HH], div_[HH];
    __shared__ double red[HH], ps[HH], pi[HH];
    __shared__ float Ts[HH + 2];
    __shared__ double sS0, sI0;

    w1s[g] = w1[f * HH + g];
    b1s[g] = b1[f * HH + g];
    Ts[g + 1] = g_tsort[f * HH + g];
    if (g == 0) { Ts[0] = -finf(); Ts[HH + 1] = finf(); }
    __syncthreads();

    const float Tlo = Ts[s], Thi = Ts[s + 1];
    const bool loI = isinf(Tlo), hiI = isinf(Thi);
    float xm;
    if (!loI && !hiI)      xm = 0.5f * Tlo + 0.5f * Thi;
    else if (loI && hiI)   xm = 0.f;
    else if (loI)          xm = Thi - 1.f;
    else                   xm = Tlo + 1.f;

    // alpha_g, beta'_g for this segment (active set fixed within segment)
    float a = 0.f, be = 0.f;
    #pragma unroll 8
    for (int h = 0; h < HH; ++h) {
        if (fmaf(xm, w1s[h], b1s[h]) > 0.f) {   // uniform branch over block
            float w2v = __ldg(w2 + f * HH * HH + h * HH + g);
            a  = fmaf(w1s[h], w2v, a);
            be = fmaf(b1s[h], w2v, be);
        }
    }
    be += __ldg(b2 + f * HH + g);
    const float w3v = __ldg(w3 + f * HH + g);

    // classify relu_g within (Tlo, Thi)
    bool ev = false, baseAct = false;
    float kink = finf(), dsl = 0.f, din = 0.f;
    if (a > 0.f) {
        float xs = -be / a;
        if (xs <= Tlo) baseAct = true;
        else if (xs < Thi) { ev = true; kink = xs; dsl = w3v * a; din = w3v * be; }
    } else if (a < 0.f) {
        float xs = -be / a;
        if (xs >= Thi) baseAct = true;
        else if (xs > Tlo) { ev = true; baseAct = true;
                             kink = xs; dsl = -w3v * a; din = -w3v * be; }
    } else {
        if (be > 0.f) baseAct = true;
    }

    // S0/I0 at segment start (fp64 reduce)
    red[g] = baseAct ? (double)(w3v * a) : 0.0;
    __syncthreads();
    for (int o = 32; o > 0; o >>= 1) { if (g < o) red[g] += red[g + o]; __syncthreads(); }
    if (g == 0) sS0 = red[0];
    __syncthreads();
    red[g] = baseAct ? (double)(w3v * be) : 0.0;
    __syncthreads();
    for (int o = 32; o > 0; o >>= 1) { if (g < o) red[g] += red[g + o]; __syncthreads(); }
    if (g == 0) sI0 = red[0] + (double)__ldg(b3 + f);
    const int n = __syncthreads_count(ev ? 1 : 0);

    kk[g] = kink; dsv[g] = dsl; div_[g] = din;
    __syncthreads();

    // bitonic sort 64 (keys kk asc; non-events padded +inf)
    for (int k = 2; k <= HH; k <<= 1)
        for (int j = k >> 1; j > 0; j >>= 1) {
            int ixj = g ^ j;
            if (ixj > g) {
                bool up = ((g & k) == 0);
                if ((kk[g] > kk[ixj]) == up) {
                    float t0;
                    t0 = kk[g];   kk[g] = kk[ixj];     kk[ixj] = t0;
                    t0 = dsv[g];  dsv[g] = dsv[ixj];   dsv[ixj] = t0;
                    t0 = div_[g]; div_[g] = div_[ixj]; div_[ixj] = t0;
                }
            }
            __syncthreads();
        }

    // inclusive prefix sums of deltas (fp64)
    ps[g] = (double)dsv[g]; pi[g] = (double)div_[g];
    __syncthreads();
    for (int o = 1; o < HH; o <<= 1) {
        double vs = (g >= o) ? ps[g - o] : 0.0;
        double vi = (g >= o) ? pi[g - o] : 0.0;
        __syncthreads();
        ps[g] += vs; pi[g] += vi;
        __syncthreads();
    }

    const int fs = f * 65 + s;
    if (g == 0) {
        stage_n[fs] = n;
        stage_SI[fs * 65] = make_float2((float)sS0, (float)sI0);
    }
    if (g < n) {
        stage_kinks[fs * 64 + g] = kk[g];
        stage_SI[fs * 65 + g + 1] =
            make_float2((float)(sS0 + ps[g]), (float)(sI0 + pi[g]));
    }
}

// ---- K2: concatenate per-segment tables (naturally globally sorted) ----
__global__ void compact_kernel() {
    const int f = blockIdx.x;
    const int tid = threadIdx.x;
    __shared__ int offX[66];
    __shared__ int nsh[65];
    if (tid < 65) nsh[tid] = stage_n[f * 65 + tid];
    __syncthreads();
    if (tid == 0) {
        int c = 0;
        for (int s = 0; s < 65; ++s) { offX[s] = c; c += nsh[s] + (s < 64 ? 1 : 0); }
        offX[65] = c;
        g_N[f] = c;
    }
    __syncthreads();
    for (int s = 0; s < 65; ++s) {
        const int n = nsh[s], ox = offX[s], fs = f * 65 + s;
        for (int j = tid; j < n; j += blockDim.x)
            g_X[f * NMAX + ox + j] = stage_kinks[fs * 64 + j];
        for (int j = tid; j <= n; j += blockDim.x)
            g_SI[f * (NMAX + 1) + ox + j] = stage_SI[fs * 65 + j];
        if (s < 64 && tid == 0)
            g_X[f * NMAX + ox + n] = g_tsort[f * HH + s];
    }
}

// ---- K2b: per-feature uniform-grid bucket table (lower_bound starts) ----
__global__ __launch_bounds__(256) void bucket_kernel() {
    __shared__ float Xs[NMAX];
    const int f = blockIdx.x;
    const int N = g_N[f];
    for (int i = threadIdx.x; i < N; i += 256) Xs[i] = g_X[f * NMAX + i];
    __syncthreads();
    const float inv = (XHI - XLO) / (float)NB;
    for (int i = threadIdx.x; i < NB; i += 256) {
        float bl = XLO + (float)i * inv;
        int lo = 0, len = N;
        while (len > 0) {                    // lower_bound: first idx with X >= bl
            int half = len >> 1;
            if (Xs[lo + half] < bl) { lo += half + 1; len -= half + 1; }
            else len = half;
        }
        g_bstart[f * NB + i] = (uint16_t)lo;
    }
}

// ---- K3: transpose x (B,F) -> (F,B) for coalesced eval ----
__global__ void xT_kernel(const float* __restrict__ x) {
    __shared__ float tile[32][33];
    const int bb = blockIdx.x * 32, ff = blockIdx.y * 32;
    const int tx = threadIdx.x, ty = threadIdx.y;
    #pragma unroll
    for (int i = ty; i < 32; i += 8)
        tile[i][tx] = x[(size_t)(bb + i) * FF + ff + tx];
    __syncthreads();
    #pragma unroll
    for (int i = ty; i < 32; i += 8)
        g_xT[(size_t)(ff + i) * BB + bb + tx] = tile[tx][i];
}

// ---- K4: eval — bucket lookup + short fix-up scan + 1 FMA per (b,f) ----
__global__ __launch_bounds__(256) void eval_kernel() {
    __shared__ float Xs[NMAX];
    __shared__ uint16_t bs[NB];
    const int f = blockIdx.y;
    const int N = g_N[f];
    for (int i = threadIdx.x; i < N; i += 256) Xs[i] = g_X[f * NMAX + i];
    {
        const uint32_t* src = (const uint32_t*)(g_bstart + f * NB);
        uint32_t* dst = (uint32_t*)bs;
        for (int i = threadIdx.x; i < NB / 2; i += 256) dst[i] = src[i];
    }
    __syncthreads();
    const float scale = (float)NB / (XHI - XLO);
    const float2* SI = g_SI + (size_t)f * (NMAX + 1);
    const float* xp = g_xT + (size_t)f * BB + blockIdx.x * 4096;
    float* cp = g_contrib + (size_t)f * BB + blockIdx.x * 4096;
    for (int r = threadIdx.x; r < 4096; r += 256) {
        float xv = __ldg(xp + r);
        int k = (int)((xv - XLO) * scale);
        k = max(0, min(NB - 1, k));
        int idx = bs[k];
        // bidirectional fix-up -> exact upper_bound (robust to bucket rounding)
        while (idx > 0 && Xs[idx - 1] > xv) --idx;
        while (idx < N && Xs[idx] <= xv) ++idx;
        float2 si = __ldg(SI + idx);
        cp[r] = fmaf(si.x, xv, si.y);
    }
}

// ---- K5: finalize ----
__global__ void finalize_kernel(const float* __restrict__ bias,
                                float* __restrict__ out) {
    int b = blockIdx.x * blockDim.x + threadIdx.x;
    if (b >= BB) return;
    float l = bias[0];
    #pragma unroll 16
    for (int f = 0; f < FF; ++f) l += g_contrib[f * BB + b];
    float p = 1.0f / (1.0f + expf(-l));
    out[2 * b + 0] = 1.0f - p;
    out[2 * b + 1] = p;
}

extern "C" void kernel_launch(void* const* d_in, const int* in_sizes, int n_in,
                              void* d_out, int out_size) {
    const float* x    = (const float*)d_in[0];
    const float* w1   = (const float*)d_in[1];
    const float* b1   = (const float*)d_in[2];
    const float* w2   = (const float*)d_in[3];
    const float* b2   = (const float*)d_in[4];
    const float* w3   = (const float*)d_in[5];
    const float* b3   = (const float*)d_in[6];
    const float* bias = (const float*)d_in[7];
    float* out = (float*)d_out;

    sort_t_kernel<<<FF, HH>>>(w1, b1);
    build_kernel<<<dim3(65, FF), HH>>>(w1, b1, w2, b2, w3, b3);
    compact_kernel<<<FF, 256>>>();
    bucket_kernel<<<FF, 256>>>();
    xT_kernel<<<dim3(BB / 32, FF / 32), dim3(32, 8)>>>(x);
    eval_kernel<<<dim3(8, FF), 256>>>();
    finalize_kernel<<<BB / 256, 256>>>(bias, out);
}